// round 1
// baseline (speedup 1.0000x reference)
#include <cuda_runtime.h>
#include <math.h>

#define BATCH 64
#define NN    512
#define HH    256
#define DNODE 38
#define TOKENS (BATCH*NN)

// ---------------- scratch (device globals; no allocation allowed) ----------
__device__ float g_node[TOKENS * DNODE];          // 5 MB
__device__ float g_mask[BATCH * NN * NN];         // 67 MB  (m[b,j,i] = mask[b,i,j])
__device__ float g_bufA[TOKENS * HH];             // 33.5 MB
__device__ float g_bufB[TOKENS * HH];
__device__ float g_bufC[TOKENS * HH];

// ---------------- K1: lidar MLP + node assembly ----------------------------
// node = concat(data[...,:18], relu(relu(lidar@lw1.T+lb1)@lw2.T+lb2))
__global__ void lidar_node_kernel(const float* __restrict__ data,
                                  const float* __restrict__ lw1,
                                  const float* __restrict__ lb1,
                                  const float* __restrict__ lw2,
                                  const float* __restrict__ lb2)
{
    int tok = blockIdx.x;
    int t = threadIdx.x;                    // 256 threads
    __shared__ float s_lidar[20];
    __shared__ float s_lf1[256];
    const float* row = data + (size_t)tok * DNODE;
    if (t < 20) s_lidar[t] = row[18 + t];
    __syncthreads();
    float acc = lb1[t];
    #pragma unroll
    for (int k = 0; k < 20; k++) acc += lw1[t * 20 + k] * s_lidar[k];
    s_lf1[t] = fmaxf(acc, 0.0f);
    __syncthreads();
    if (t < 20) {
        float a = lb2[t];
        const float* w = lw2 + t * 256;
        #pragma unroll 8
        for (int k = 0; k < 256; k++) a += w[k] * s_lf1[k];
        g_node[(size_t)tok * DNODE + 18 + t] = fmaxf(a, 0.0f);
    } else if (t < 38) {
        int c = t - 20;
        g_node[(size_t)tok * DNODE + c] = row[c];
    }
}

// ---------------- K2: adjacency mask ---------------------------------------
// m[b,j,i] = (i!=j) && sqrt(dx^2+dy^2) <= 10   (symmetric; |ang|<=pi vacuous)
__global__ void mask_kernel(const float* __restrict__ data)
{
    int b = blockIdx.x / NN;
    int j = blockIdx.x % NN;
    int i = threadIdx.x;                    // 512 threads
    __shared__ float pj[2];
    if (i < 2) pj[i] = data[((size_t)(b * NN + j)) * DNODE + i];
    __syncthreads();
    const float* ri = data + ((size_t)(b * NN + i)) * DNODE;
    float dx = ri[0] - pj[0];
    float dy = ri[1] - pj[1];
    float dist = sqrtf(dx * dx + dy * dy);
    float m = (i != j && dist <= 10.0f) ? 1.0f : 0.0f;
    g_mask[((size_t)blockIdx.x) * NN + i] = m;
}

// ---------------- generic tiled SGEMM --------------------------------------
// C[M,N] = act( A[M,K] @ B (+bias) (+res) ), batched via blockIdx.z
// TRANSB: B is [N,K] row-major (weights);  else B is [K,N] row-major.
// M must be a multiple of 64. N,K arbitrary.
template<bool TRANSB, bool RELU, bool HASBIAS, bool HASRES>
__global__ __launch_bounds__(256)
void sgemm(const float* __restrict__ A, const float* __restrict__ Bm,
           const float* __restrict__ bias, const float* __restrict__ res,
           float* __restrict__ C,
           int M, int N, int K,
           unsigned long long sA, unsigned long long sB,
           unsigned long long sR, unsigned long long sC)
{
    constexpr int BM = 64, BN = 64, BK = 16, PAD = 4;
    __shared__ float As[BK][BM + PAD];
    __shared__ float Bs[BK][BN + PAD];
    int bz = blockIdx.z;
    const float* Ab = A + (size_t)bz * sA;
    const float* Bb = Bm + (size_t)bz * sB;
    const float* Rb = HASRES ? (res + (size_t)bz * sR) : nullptr;
    float* Cb = C + (size_t)bz * sC;
    int m0 = blockIdx.y * BM, n0 = blockIdx.x * BN;
    int tid = threadIdx.x;
    int tx = tid & 15, ty = tid >> 4;

    float acc[4][4];
    #pragma unroll
    for (int i = 0; i < 4; i++)
        #pragma unroll
        for (int j = 0; j < 4; j++) acc[i][j] = 0.0f;

    for (int k0 = 0; k0 < K; k0 += BK) {
        {   // A tile: 64 rows x 16 k
            int r = tid >> 2, cb = (tid & 3) * 4;
            #pragma unroll
            for (int u = 0; u < 4; u++) {
                int kk = k0 + cb + u;
                As[cb + u][r] = (kk < K) ? Ab[(size_t)(m0 + r) * K + kk] : 0.0f;
            }
        }
        if (TRANSB) {   // B[N,K]: 64 n x 16 k
            int r = tid >> 2, cb = (tid & 3) * 4;
            #pragma unroll
            for (int u = 0; u < 4; u++) {
                int kk = k0 + cb + u;
                Bs[cb + u][r] = (kk < K && (n0 + r) < N)
                              ? Bb[(size_t)(n0 + r) * K + kk] : 0.0f;
            }
        } else {        // B[K,N]: 16 k x 64 n
            int nb = (tid & 15) * 4, c = tid >> 4;
            int kk = k0 + c;
            #pragma unroll
            for (int u = 0; u < 4; u++) {
                int n = nb + u;
                Bs[c][n] = (kk < K && (n0 + n) < N)
                         ? Bb[(size_t)kk * N + n0 + n] : 0.0f;
            }
        }
        __syncthreads();
        #pragma unroll
        for (int k = 0; k < BK; k++) {
            float4 a4 = *(const float4*)&As[k][ty * 4];
            float4 b4 = *(const float4*)&Bs[k][tx * 4];
            float av[4] = {a4.x, a4.y, a4.z, a4.w};
            float bv[4] = {b4.x, b4.y, b4.z, b4.w};
            #pragma unroll
            for (int i = 0; i < 4; i++)
                #pragma unroll
                for (int j = 0; j < 4; j++)
                    acc[i][j] += av[i] * bv[j];
        }
        __syncthreads();
    }

    #pragma unroll
    for (int i = 0; i < 4; i++) {
        int row = m0 + ty * 4 + i;
        #pragma unroll
        for (int j = 0; j < 4; j++) {
            int col = n0 + tx * 4 + j;
            if (col < N) {
                float v = acc[i][j];
                if (HASBIAS) v += bias[col];
                if (HASRES)  v += Rb[(size_t)row * N + col];
                if (RELU)    v = fmaxf(v, 0.0f);
                Cb[(size_t)row * N + col] = v;
            }
        }
    }
}

// ---------------- LN: out = LN(x+y)*g + b  (two-pass, matches mean((x-m)^2))
__global__ void ln_kernel(const float* __restrict__ x, const float* __restrict__ y,
                          const float* __restrict__ g, const float* __restrict__ b,
                          float* __restrict__ out)
{
    int tok = blockIdx.x, t = threadIdx.x;   // 256 threads
    size_t base = (size_t)tok * HH;
    float v = x[base + t] + y[base + t];
    __shared__ float red1[8], red2[8];
    float s = v;
    #pragma unroll
    for (int o = 16; o > 0; o >>= 1) s += __shfl_xor_sync(~0u, s, o);
    if ((t & 31) == 0) red1[t >> 5] = s;
    __syncthreads();
    float tot = 0.0f;
    #pragma unroll
    for (int w = 0; w < 8; w++) tot += red1[w];
    float mean = tot * (1.0f / 256.0f);
    float d = v - mean;
    float s2 = d * d;
    #pragma unroll
    for (int o = 16; o > 0; o >>= 1) s2 += __shfl_xor_sync(~0u, s2, o);
    if ((t & 31) == 0) red2[t >> 5] = s2;
    __syncthreads();
    float tot2 = 0.0f;
    #pragma unroll
    for (int w = 0; w < 8; w++) tot2 += red2[w];
    float var = tot2 * (1.0f / 256.0f);
    out[base + t] = d / sqrtf(var + 1e-5f) * g[t] + b[t];
}

// ---------------- final head: out[tok, o] = h[tok] . fc_w[o] + fc_b[o] -----
__global__ void fc_kernel(const float* __restrict__ h, const float* __restrict__ W,
                          const float* __restrict__ bias, float* __restrict__ out)
{
    int tok = blockIdx.x;
    int w = threadIdx.x >> 5, lane = threadIdx.x & 31;   // 160 threads = 5 warps
    const float* hr = h + (size_t)tok * HH;
    const float* wr = W + w * HH;
    float s = 0.0f;
    #pragma unroll
    for (int k = 0; k < 8; k++) s += hr[lane + 32 * k] * wr[lane + 32 * k];
    #pragma unroll
    for (int o = 16; o > 0; o >>= 1) s += __shfl_xor_sync(~0u, s, o);
    if (lane == 0) out[(size_t)tok * 5 + w] = s + bias[w];
}

// ---------------- launch ----------------------------------------------------
extern "C" void kernel_launch(void* const* d_in, const int* in_sizes, int n_in,
                              void* d_out, int out_size)
{
    const float* data   = (const float*)d_in[0];
    const float* lw1    = (const float*)d_in[1];
    const float* lb1    = (const float*)d_in[2];
    const float* lw2    = (const float*)d_in[3];
    const float* lb2    = (const float*)d_in[4];
    const float* g1w1   = (const float*)d_in[5];
    const float* g1b1   = (const float*)d_in[6];
    const float* g1w2   = (const float*)d_in[7];
    const float* g1b2   = (const float*)d_in[8];
    const float* g2w1   = (const float*)d_in[9];
    const float* g2b1   = (const float*)d_in[10];
    const float* g2w2   = (const float*)d_in[11];
    const float* g2b2   = (const float*)d_in[12];
    const float* t_in_w = (const float*)d_in[13];
    const float* t_in_b = (const float*)d_in[14];
    const float* t_out_w= (const float*)d_in[15];
    const float* t_out_b= (const float*)d_in[16];
    const float* t_ln1_g= (const float*)d_in[17];
    const float* t_ln1_b= (const float*)d_in[18];
    const float* t_ff1_w= (const float*)d_in[19];
    const float* t_ff1_b= (const float*)d_in[20];
    const float* t_ff2_w= (const float*)d_in[21];
    const float* t_ff2_b= (const float*)d_in[22];
    const float* t_ln2_g= (const float*)d_in[23];
    const float* t_ln2_b= (const float*)d_in[24];
    const float* fc_w   = (const float*)d_in[25];
    const float* fc_b   = (const float*)d_in[26];
    float* out = (float*)d_out;

    float *node, *mask, *bufA, *bufB, *bufC;
    cudaGetSymbolAddress((void**)&node, g_node);
    cudaGetSymbolAddress((void**)&mask, g_mask);
    cudaGetSymbolAddress((void**)&bufA, g_bufA);
    cudaGetSymbolAddress((void**)&bufB, g_bufB);
    cudaGetSymbolAddress((void**)&bufC, g_bufC);

    // 1. lidar MLP -> node
    lidar_node_kernel<<<TOKENS, 256>>>(data, lw1, lb1, lw2, lb2);
    // 2. adjacency mask
    mask_kernel<<<BATCH * NN, NN>>>(data);

    // 3. agg0 = node + m @ node   (batched, N=38)
    {
        dim3 grid(1, NN / 64, BATCH);
        sgemm<false, false, false, true><<<grid, 256>>>(
            mask, node, nullptr, node, bufA,
            NN, DNODE, NN,
            (unsigned long long)(NN * NN), (unsigned long long)(NN * DNODE),
            (unsigned long long)(NN * DNODE), (unsigned long long)(NN * DNODE));
    }
    // 4. GIN1 MLP
    {
        dim3 grid(HH / 64, TOKENS / 64, 1);
        sgemm<true, true, true, false><<<grid, 256>>>(
            bufA, g1w1, g1b1, nullptr, bufB, TOKENS, HH, DNODE, 0, 0, 0, 0);
        sgemm<true, true, true, false><<<grid, 256>>>(
            bufB, g1w2, g1b2, nullptr, bufC, TOKENS, HH, HH, 0, 0, 0, 0);
    }
    // 5. agg1 = h + m @ h  (batched, N=256)
    {
        dim3 grid(HH / 64, NN / 64, BATCH);
        sgemm<false, false, false, true><<<grid, 256>>>(
            mask, bufC, nullptr, bufC, bufA,
            NN, HH, NN,
            (unsigned long long)(NN * NN), (unsigned long long)(NN * HH),
            (unsigned long long)(NN * HH), (unsigned long long)(NN * HH));
    }
    // 6. GIN2 MLP
    {
        dim3 grid(HH / 64, TOKENS / 64, 1);
        sgemm<true, true, true, false><<<grid, 256>>>(
            bufA, g2w1, g2b1, nullptr, bufB, TOKENS, HH, HH, 0, 0, 0, 0);
        sgemm<true, true, true, false><<<grid, 256>>>(
            bufB, g2w2, g2b2, nullptr, bufC, TOKENS, HH, HH, 0, 0, 0, 0);
    }
    // 7. transformer layers (h lives in bufC at loop top)
    dim3 gridT(HH / 64, TOKENS / 64, 1);
    for (int l = 0; l < 2; l++) {
        const float* Wv = t_in_w + (size_t)l * 768 * HH + (size_t)512 * HH;
        const float* bv = t_in_b + (size_t)l * 768 + 512;
        const float* Wo = t_out_w + (size_t)l * HH * HH;
        const float* bo = t_out_b + (size_t)l * HH;
        const float* l1g = t_ln1_g + (size_t)l * HH;
        const float* l1b = t_ln1_b + (size_t)l * HH;
        const float* W1 = t_ff1_w + (size_t)l * HH * HH;
        const float* b1 = t_ff1_b + (size_t)l * HH;
        const float* W2 = t_ff2_w + (size_t)l * HH * HH;
        const float* b2 = t_ff2_b + (size_t)l * HH;
        const float* l2g = t_ln2_g + (size_t)l * HH;
        const float* l2b = t_ln2_b + (size_t)l * HH;

        // v = h @ Wv.T + bv      -> bufA
        sgemm<true, false, true, false><<<gridT, 256>>>(
            bufC, Wv, bv, nullptr, bufA, TOKENS, HH, HH, 0, 0, 0, 0);
        // attn = v @ Wo.T + bo   -> bufB
        sgemm<true, false, true, false><<<gridT, 256>>>(
            bufA, Wo, bo, nullptr, bufB, TOKENS, HH, HH, 0, 0, 0, 0);
        // h = LN(h + attn)       -> bufA
        ln_kernel<<<TOKENS, 256>>>(bufC, bufB, l1g, l1b, bufA);
        // ff1 = relu(h @ W1.T + b1) -> bufB
        sgemm<true, true, true, false><<<gridT, 256>>>(
            bufA, W1, b1, nullptr, bufB, TOKENS, HH, HH, 0, 0, 0, 0);
        // ff2 = ff1 @ W2.T + b2  -> bufC
        sgemm<true, false, true, false><<<gridT, 256>>>(
            bufB, W2, b2, nullptr, bufC, TOKENS, HH, HH, 0, 0, 0, 0);
        // h = LN(h + ff2)        -> bufC  (in-place on y is safe: per-token block)
        ln_kernel<<<TOKENS, 256>>>(bufA, bufC, l2g, l2b, bufC);
    }
    // 8. head
    fc_kernel<<<TOKENS, 160>>>(bufC, fc_w, fc_b, out);
    (void)in_sizes; (void)n_in; (void)out_size;
}

// round 2
// speedup vs baseline: 1.9418x; 1.9418x over previous
#include <cuda_runtime.h>
#include <math.h>

#define BATCH 64
#define NN    512
#define HH    256
#define DNODE 38
#define TOKENS (BATCH*NN)

// ---------------- scratch (device globals; no allocation allowed) ----------
__device__ float g_node[TOKENS * DNODE];          // 5 MB
__device__ float g_bufA[TOKENS * HH];             // 33.5 MB
__device__ float g_bufB[TOKENS * HH];
__device__ float g_bufC[TOKENS * HH];
__device__ float g_S[BATCH * HH];                 // column sums

// ---------------- K1: lidar MLP + node assembly ----------------------------
// node = concat(data[...,:18], relu(relu(lidar@lw1.T+lb1)@lw2.T+lb2))
__global__ void lidar_node_kernel(const float* __restrict__ data,
                                  const float* __restrict__ lw1,
                                  const float* __restrict__ lb1,
                                  const float* __restrict__ lw2,
                                  const float* __restrict__ lb2)
{
    int tok = blockIdx.x;
    int t = threadIdx.x;                    // 256 threads
    __shared__ float s_lidar[20];
    __shared__ float s_lf1[256];
    const float* row = data + (size_t)tok * DNODE;
    if (t < 20) s_lidar[t] = row[18 + t];
    if (t < 18) g_node[(size_t)tok * DNODE + t] = row[t];
    __syncthreads();
    float acc = lb1[t];
    #pragma unroll
    for (int k = 0; k < 20; k++) acc += lw1[t * 20 + k] * s_lidar[k];
    s_lf1[t] = fmaxf(acc, 0.0f);
    __syncthreads();
    int wid = t >> 5, lane = t & 31;
    for (int o = wid; o < 20; o += 8) {
        const float* w = lw2 + o * 256;
        float s = 0.0f;
        #pragma unroll
        for (int k = 0; k < 8; k++) s += s_lf1[lane + 32 * k] * w[lane + 32 * k];
        #pragma unroll
        for (int off = 16; off > 0; off >>= 1) s += __shfl_xor_sync(~0u, s, off);
        if (lane == 0)
            g_node[(size_t)tok * DNODE + 18 + o] = fmaxf(s + lb2[o], 0.0f);
    }
}

// ---------------- column sums: S[b,d] = sum_j h[b,j,d] ---------------------
template<int D>
__global__ void colsum_kernel(const float* __restrict__ h, float* __restrict__ S)
{
    int b = blockIdx.x;
    int t = threadIdx.x;            // 256
    if (t >= D) return;
    const float* p = h + (size_t)b * NN * D + t;
    float s = 0.0f;
    #pragma unroll 8
    for (int j = 0; j < NN; j++) s += p[(size_t)j * D];
    S[b * D + t] = s;
}

// ---------------- aggregation via colsum + sparse far-pair correction ------
// out[b,j,:] = S[b,:] - sum_{i != j, dist(i,j) > 10} h[b,i,:]
// (equivalent to h + mask @ h since |ang|<=pi is vacuous and mask symmetric)
template<int D>
__global__ void agg_kernel(const float* __restrict__ data,
                           const float* __restrict__ S,
                           const float* __restrict__ h,
                           float* __restrict__ out)
{
    int b = blockIdx.x;
    int jc = blockIdx.y;            // 8 chunks of 64 j
    int tid = threadIdx.x;          // 512
    __shared__ float px[NN], py[NN];
    __shared__ float sS[D];
    __shared__ int s_cnt;
    __shared__ short s_list[NN];
    const float* db = data + (size_t)b * NN * DNODE;
    px[tid] = db[(size_t)tid * DNODE + 0];
    py[tid] = db[(size_t)tid * DNODE + 1];
    if (tid < D) sS[tid] = S[b * D + tid];
    __syncthreads();
    for (int jj = 0; jj < 64; jj++) {
        int j = jc * 64 + jj;
        float dx = px[tid] - px[j];
        float dy = py[tid] - py[j];
        bool far = (tid != j) && (sqrtf(dx * dx + dy * dy) > 10.0f);
        if (tid == 0) s_cnt = 0;
        int nf = __syncthreads_count(far);
        if (nf == 0) {
            if (tid < D) out[((size_t)(b * NN + j)) * D + tid] = sS[tid];
        } else {
            if (far) { int p = atomicAdd(&s_cnt, 1); s_list[p] = (short)tid; }
            __syncthreads();
            if (tid < D) {
                float v = sS[tid];
                for (int l = 0; l < nf; l++)
                    v -= h[((size_t)(b * NN + s_list[l])) * D + tid];
                out[((size_t)(b * NN + j)) * D + tid] = v;
            }
            __syncthreads();
        }
    }
}

// ---------------- SGEMM: C[M,N] = act(A[M,K] @ W[N,K]^T + bias) ------------
// 128x128 tile, 8x8 microtile (split-64), BK=16. M%128==0, N%128==0.
template<bool VEC, bool RELU>
__global__ __launch_bounds__(256)
void sgemm_t(const float* __restrict__ A, const float* __restrict__ W,
             const float* __restrict__ bias, float* __restrict__ C,
             int M, int N, int K)
{
    constexpr int BM = 128, BN = 128, BK = 16, LD = BM + 4;
    __shared__ float As[BK][LD];
    __shared__ float Bs[BK][LD];
    int m0 = blockIdx.y * BM, n0 = blockIdx.x * BN;
    int tid = threadIdx.x;
    int tx = tid & 15, ty = tid >> 4;
    int lr = tid >> 1;              // 0..127
    int lk = (tid & 1) * 8;         // 0 or 8

    float acc[8][8];
    #pragma unroll
    for (int i = 0; i < 8; i++)
        #pragma unroll
        for (int j = 0; j < 8; j++) acc[i][j] = 0.0f;

    const float* ap = A + (size_t)(m0 + lr) * K + lk;
    const float* wp = W + (size_t)(n0 + lr) * K + lk;

    for (int k0 = 0; k0 < K; k0 += BK) {
        if (VEC) {
            float4 a0 = *(const float4*)(ap + k0);
            float4 a1 = *(const float4*)(ap + k0 + 4);
            float4 b0 = *(const float4*)(wp + k0);
            float4 b1 = *(const float4*)(wp + k0 + 4);
            As[lk + 0][lr] = a0.x; As[lk + 1][lr] = a0.y;
            As[lk + 2][lr] = a0.z; As[lk + 3][lr] = a0.w;
            As[lk + 4][lr] = a1.x; As[lk + 5][lr] = a1.y;
            As[lk + 6][lr] = a1.z; As[lk + 7][lr] = a1.w;
            Bs[lk + 0][lr] = b0.x; Bs[lk + 1][lr] = b0.y;
            Bs[lk + 2][lr] = b0.z; Bs[lk + 3][lr] = b0.w;
            Bs[lk + 4][lr] = b1.x; Bs[lk + 5][lr] = b1.y;
            Bs[lk + 6][lr] = b1.z; Bs[lk + 7][lr] = b1.w;
        } else {
            #pragma unroll
            for (int u = 0; u < 8; u++) {
                int kk = k0 + lk + u;
                As[lk + u][lr] = (kk < K) ? ap[kk - lk] : 0.0f;
                Bs[lk + u][lr] = (kk < K) ? wp[kk - lk] : 0.0f;
            }
        }
        __syncthreads();
        #pragma unroll
        for (int k = 0; k < BK; k++) {
            float a[8], b[8];
            *(float4*)&a[0] = *(const float4*)&As[k][ty * 4];
            *(float4*)&a[4] = *(const float4*)&As[k][64 + ty * 4];
            *(float4*)&b[0] = *(const float4*)&Bs[k][tx * 4];
            *(float4*)&b[4] = *(const float4*)&Bs[k][64 + tx * 4];
            #pragma unroll
            for (int i = 0; i < 8; i++)
                #pragma unroll
                for (int j = 0; j < 8; j++)
                    acc[i][j] += a[i] * b[j];
        }
        __syncthreads();
    }

    float bv[8];
    #pragma unroll
    for (int j = 0; j < 8; j++) {
        int c = (j < 4) ? (tx * 4 + j) : (64 + tx * 4 + j - 4);
        bv[j] = bias[n0 + c];
    }
    #pragma unroll
    for (int i = 0; i < 8; i++) {
        int r = m0 + ((i < 4) ? (ty * 4 + i) : (64 + ty * 4 + i - 4));
        float* cr = C + (size_t)r * N + n0;
        float4 v0, v1;
        v0.x = acc[i][0] + bv[0]; v0.y = acc[i][1] + bv[1];
        v0.z = acc[i][2] + bv[2]; v0.w = acc[i][3] + bv[3];
        v1.x = acc[i][4] + bv[4]; v1.y = acc[i][5] + bv[5];
        v1.z = acc[i][6] + bv[6]; v1.w = acc[i][7] + bv[7];
        if (RELU) {
            v0.x = fmaxf(v0.x, 0.f); v0.y = fmaxf(v0.y, 0.f);
            v0.z = fmaxf(v0.z, 0.f); v0.w = fmaxf(v0.w, 0.f);
            v1.x = fmaxf(v1.x, 0.f); v1.y = fmaxf(v1.y, 0.f);
            v1.z = fmaxf(v1.z, 0.f); v1.w = fmaxf(v1.w, 0.f);
        }
        *(float4*)&cr[tx * 4]      = v0;
        *(float4*)&cr[64 + tx * 4] = v1;
    }
}

// ---------------- LN: out = LN(x+y)*g + b ----------------------------------
__global__ void ln_kernel(const float* __restrict__ x, const float* __restrict__ y,
                          const float* __restrict__ g, const float* __restrict__ b,
                          float* __restrict__ out)
{
    int tok = blockIdx.x, t = threadIdx.x;   // 256 threads
    size_t base = (size_t)tok * HH;
    float v = x[base + t] + y[base + t];
    __shared__ float red1[8], red2[8];
    float s = v;
    #pragma unroll
    for (int o = 16; o > 0; o >>= 1) s += __shfl_xor_sync(~0u, s, o);
    if ((t & 31) == 0) red1[t >> 5] = s;
    __syncthreads();
    float tot = 0.0f;
    #pragma unroll
    for (int w = 0; w < 8; w++) tot += red1[w];
    float mean = tot * (1.0f / 256.0f);
    float d = v - mean;
    float s2 = d * d;
    #pragma unroll
    for (int o = 16; o > 0; o >>= 1) s2 += __shfl_xor_sync(~0u, s2, o);
    if ((t & 31) == 0) red2[t >> 5] = s2;
    __syncthreads();
    float tot2 = 0.0f;
    #pragma unroll
    for (int w = 0; w < 8; w++) tot2 += red2[w];
    float var = tot2 * (1.0f / 256.0f);
    out[base + t] = d / sqrtf(var + 1e-5f) * g[t] + b[t];
}

// ---------------- final head ------------------------------------------------
__global__ void fc_kernel(const float* __restrict__ h, const float* __restrict__ W,
                          const float* __restrict__ bias, float* __restrict__ out)
{
    int tok = blockIdx.x;
    int w = threadIdx.x >> 5, lane = threadIdx.x & 31;   // 160 threads
    const float* hr = h + (size_t)tok * HH;
    const float* wr = W + w * HH;
    float s = 0.0f;
    #pragma unroll
    for (int k = 0; k < 8; k++) s += hr[lane + 32 * k] * wr[lane + 32 * k];
    #pragma unroll
    for (int o = 16; o > 0; o >>= 1) s += __shfl_xor_sync(~0u, s, o);
    if (lane == 0) out[(size_t)tok * 5 + w] = s + bias[w];
}

// ---------------- launch ----------------------------------------------------
extern "C" void kernel_launch(void* const* d_in, const int* in_sizes, int n_in,
                              void* d_out, int out_size)
{
    const float* data   = (const float*)d_in[0];
    const float* lw1    = (const float*)d_in[1];
    const float* lb1    = (const float*)d_in[2];
    const float* lw2    = (const float*)d_in[3];
    const float* lb2    = (const float*)d_in[4];
    const float* g1w1   = (const float*)d_in[5];
    const float* g1b1   = (const float*)d_in[6];
    const float* g1w2   = (const float*)d_in[7];
    const float* g1b2   = (const float*)d_in[8];
    const float* g2w1   = (const float*)d_in[9];
    const float* g2b1   = (const float*)d_in[10];
    const float* g2w2   = (const float*)d_in[11];
    const float* g2b2   = (const float*)d_in[12];
    const float* t_in_w = (const float*)d_in[13];
    const float* t_in_b = (const float*)d_in[14];
    const float* t_out_w= (const float*)d_in[15];
    const float* t_out_b= (const float*)d_in[16];
    const float* t_ln1_g= (const float*)d_in[17];
    const float* t_ln1_b= (const float*)d_in[18];
    const float* t_ff1_w= (const float*)d_in[19];
    const float* t_ff1_b= (const float*)d_in[20];
    const float* t_ff2_w= (const float*)d_in[21];
    const float* t_ff2_b= (const float*)d_in[22];
    const float* t_ln2_g= (const float*)d_in[23];
    const float* t_ln2_b= (const float*)d_in[24];
    const float* fc_w   = (const float*)d_in[25];
    const float* fc_b   = (const float*)d_in[26];
    float* out = (float*)d_out;

    float *node, *bufA, *bufB, *bufC, *S;
    cudaGetSymbolAddress((void**)&node, g_node);
    cudaGetSymbolAddress((void**)&bufA, g_bufA);
    cudaGetSymbolAddress((void**)&bufB, g_bufB);
    cudaGetSymbolAddress((void**)&bufC, g_bufC);
    cudaGetSymbolAddress((void**)&S,    g_S);

    dim3 gridG(HH / 128, TOKENS / 128, 1);
    dim3 gridA(BATCH, 8, 1);

    // 1. lidar MLP -> node
    lidar_node_kernel<<<TOKENS, 256>>>(data, lw1, lb1, lw2, lb2);
    // 2. agg0 = node + mask @ node  (== colsum - far corrections)
    colsum_kernel<DNODE><<<BATCH, 256>>>(node, S);
    agg_kernel<DNODE><<<gridA, NN>>>(data, S, node, bufA);
    // 3. GIN1 MLP
    sgemm_t<false, true><<<gridG, 256>>>(bufA, g1w1, g1b1, bufB, TOKENS, HH, DNODE);
    sgemm_t<true,  true><<<gridG, 256>>>(bufB, g1w2, g1b2, bufC, TOKENS, HH, HH);
    // 4. agg1
    colsum_kernel<HH><<<BATCH, 256>>>(bufC, S);
    agg_kernel<HH><<<gridA, NN>>>(data, S, bufC, bufA);
    // 5. GIN2 MLP
    sgemm_t<true, true><<<gridG, 256>>>(bufA, g2w1, g2b1, bufB, TOKENS, HH, HH);
    sgemm_t<true, true><<<gridG, 256>>>(bufB, g2w2, g2b2, bufC, TOKENS, HH, HH);
    // 6. transformer layers (h in bufC at loop top)
    for (int l = 0; l < 2; l++) {
        const float* Wv = t_in_w + (size_t)l * 768 * HH + (size_t)512 * HH;
        const float* bv = t_in_b + (size_t)l * 768 + 512;
        const float* Wo = t_out_w + (size_t)l * HH * HH;
        const float* bo = t_out_b + (size_t)l * HH;
        const float* l1g = t_ln1_g + (size_t)l * HH;
        const float* l1b = t_ln1_b + (size_t)l * HH;
        const float* W1 = t_ff1_w + (size_t)l * HH * HH;
        const float* b1 = t_ff1_b + (size_t)l * HH;
        const float* W2 = t_ff2_w + (size_t)l * HH * HH;
        const float* b2 = t_ff2_b + (size_t)l * HH;
        const float* l2g = t_ln2_g + (size_t)l * HH;
        const float* l2b = t_ln2_b + (size_t)l * HH;

        sgemm_t<true, false><<<gridG, 256>>>(bufC, Wv, bv, bufA, TOKENS, HH, HH);
        sgemm_t<true, false><<<gridG, 256>>>(bufA, Wo, bo, bufB, TOKENS, HH, HH);
        ln_kernel<<<TOKENS, 256>>>(bufC, bufB, l1g, l1b, bufA);
        sgemm_t<true, true ><<<gridG, 256>>>(bufA, W1, b1, bufB, TOKENS, HH, HH);
        sgemm_t<true, false><<<gridG, 256>>>(bufB, W2, b2, bufC, TOKENS, HH, HH);
        ln_kernel<<<TOKENS, 256>>>(bufA, bufC, l2g, l2b, bufC);
    }
    // 7. head
    fc_kernel<<<TOKENS, 160>>>(bufC, fc_w, fc_b, out);
    (void)in_sizes; (void)n_in; (void)out_size;
}

// round 4
// speedup vs baseline: 2.9430x; 1.5156x over previous
#include <cuda_runtime.h>
#include <cuda_bf16.h>
#include <math.h>
#include <stdint.h>

#define BATCH 64
#define NN    512
#define HH    256
#define DNODE 38
#define TOKENS (BATCH*NN)

// ---------------- scratch (device globals) ----------------------------------
__device__ float g_node[TOKENS * DNODE];
__device__ float g_bufA[TOKENS * HH];
__device__ float g_bufB[TOKENS * HH];
__device__ float g_bufC[TOKENS * HH];
__device__ float g_S[BATCH * HH];
__device__ __nv_bfloat16 g_h0hi[TOKENS * HH];
__device__ __nv_bfloat16 g_h0lo[TOKENS * HH];
__device__ __nv_bfloat16 g_h1hi[TOKENS * HH];
__device__ __nv_bfloat16 g_h1lo[TOKENS * HH];
#define NWSLOT 11
__device__ __nv_bfloat16 g_Whi[NWSLOT * HH * HH];
__device__ __nv_bfloat16 g_Wlo[NWSLOT * HH * HH];

// ---------------- PTX helpers (sm_103 BASE ISA only: no tcgen05) ------------
__device__ __forceinline__ uint32_t smem_u32(const void* p) {
    uint32_t a;
    asm("{ .reg .u64 t; cvta.to.shared.u64 t, %1; cvt.u32.u64 %0, t; }"
        : "=r"(a) : "l"(p));
    return a;
}
#define CP_ASYNC16(dst, src) \
    asm volatile("cp.async.cg.shared.global [%0], [%1], 16;" \
                 :: "r"(dst), "l"(src) : "memory")
#define CP_COMMIT() asm volatile("cp.async.commit_group;" ::: "memory")
#define CP_WAIT1()  asm volatile("cp.async.wait_group 1;" ::: "memory")
#define CP_WAIT0()  asm volatile("cp.async.wait_group 0;" ::: "memory")
#define LDSM_X4(r0, r1, r2, r3, addr) \
    asm volatile("ldmatrix.sync.aligned.m8n8.x4.shared.b16 {%0,%1,%2,%3}, [%4];" \
                 : "=r"(r0), "=r"(r1), "=r"(r2), "=r"(r3) : "r"(addr))

__device__ __forceinline__ void mma_bf16(float* d, const uint32_t* a, const uint32_t* b) {
    asm volatile(
        "mma.sync.aligned.m16n8k16.row.col.f32.bf16.bf16.f32 "
        "{%0,%1,%2,%3}, {%4,%5,%6,%7}, {%8,%9}, {%0,%1,%2,%3};"
        : "+f"(d[0]), "+f"(d[1]), "+f"(d[2]), "+f"(d[3])
        : "r"(a[0]), "r"(a[1]), "r"(a[2]), "r"(a[3]), "r"(b[0]), "r"(b[1]));
}

__device__ __forceinline__ void split_pack(float f0, float f1, uint32_t& hw, uint32_t& lw) {
    __nv_bfloat162 h2 = __floats2bfloat162_rn(f0, f1);
    float l0 = f0 - __bfloat162float(h2.x);
    float l1 = f1 - __bfloat162float(h2.y);
    __nv_bfloat162 l2 = __floats2bfloat162_rn(l0, l1);
    hw = *(uint32_t*)&h2;
    lw = *(uint32_t*)&l2;
}

// ---------------- HMMA split-bf16 GEMM ---------------------------------------
// C[M,256] = act( (Ahi+Alo)[M,256] @ (Whi+Wlo)[256,256]^T + bias )
// tile 128x128, BK=64, cp.async double buffer, 8 warps (4m x 2n), warp 32x64
template<bool RELU, bool WF32, bool WHILO>
__global__ __launch_bounds__(256, 1)
void mgemm(const __nv_bfloat16* __restrict__ Ahi, const __nv_bfloat16* __restrict__ Alo,
           const __nv_bfloat16* __restrict__ Whi, const __nv_bfloat16* __restrict__ Wlo,
           const float* __restrict__ bias,
           float* __restrict__ Cf32,
           __nv_bfloat16* __restrict__ Chi, __nv_bfloat16* __restrict__ Clo)
{
    constexpr int STAGE = 64 * 1024;
    constexpr int OFF_AH = 0, OFF_AL = 16 * 1024, OFF_WH = 32 * 1024, OFF_WL = 48 * 1024;
    extern __shared__ char dynsmem[];
    uint32_t smu = smem_u32(dynsmem);
    __shared__ float s_bias[128];

    int tid = threadIdx.x;
    int wid = tid >> 5, l = tid & 31;
    int wm = wid & 3, wn = wid >> 2;      // 4 m-warps x 2 n-warps
    int n0 = blockIdx.x * 128;
    int m0 = blockIdx.y * 128;

    if (tid < 128) s_bias[tid] = bias[n0 + tid];

    const char* Ahb = (const char*)(Ahi + (size_t)m0 * HH);
    const char* Alb = (const char*)(Alo + (size_t)m0 * HH);
    const char* Whb = (const char*)(Whi + (size_t)n0 * HH);
    const char* Wlb = (const char*)(Wlo + (size_t)n0 * HH);

    // per-thread load mapping: 4 16B chunks per array per stage
    int lr = tid >> 1;                    // row 0..127 (2 threads/row)
    // each thread covers 4 of the 8 chunks in its row:
    int jb = (tid & 1) * 4;               // chunk base 0 or 4

    auto load_stage = [&](int c, int s) {
        int kb = c * 128;                 // byte offset in K
        uint32_t base = smu + s * STAGE;
        uint32_t rbase = (uint32_t)lr * 128;
        int sw = lr & 7;
        #pragma unroll
        for (int u = 0; u < 4; u++) {
            int j = jb + u;
            uint32_t dsto = rbase + (uint32_t)((j ^ sw) << 4);
            size_t srco = (size_t)lr * 512 + kb + j * 16;
            CP_ASYNC16(base + OFF_AH + dsto, Ahb + srco);
            CP_ASYNC16(base + OFF_AL + dsto, Alb + srco);
            CP_ASYNC16(base + OFF_WH + dsto, Whb + srco);
            CP_ASYNC16(base + OFF_WL + dsto, Wlb + srco);
        }
    };

    float acc[2][8][4];
    #pragma unroll
    for (int i = 0; i < 2; i++)
        #pragma unroll
        for (int j = 0; j < 8; j++)
            #pragma unroll
            for (int q = 0; q < 4; q++) acc[i][j][q] = 0.0f;

    // ldmatrix lane row offsets (within tile) precomputed
    int a_row[2], b_row[4];
    #pragma unroll
    for (int mt = 0; mt < 2; mt++)
        a_row[mt] = wm * 32 + mt * 16 + (l & 7) + ((l & 8) ? 8 : 0);
    #pragma unroll
    for (int g = 0; g < 4; g++)
        b_row[g] = wn * 64 + g * 16 + (l & 7) + ((l & 16) ? 8 : 0);
    int a_ch = (l >> 4);          // 0/1 extra chunk for A quads
    int b_ch = (l >> 3) & 1;      // 0/1 extra chunk for B quads

    load_stage(0, 0);
    CP_COMMIT();

    for (int c = 0; c < 4; c++) {
        if (c < 3) { load_stage(c + 1, (c + 1) & 1); CP_COMMIT(); CP_WAIT1(); }
        else       { CP_WAIT0(); }
        __syncthreads();
        uint32_t base = smu + (c & 1) * STAGE;
        #pragma unroll
        for (int ks = 0; ks < 4; ks++) {
            uint32_t ah[2][4], al[2][4], bh[8][2], bl[8][2];
            #pragma unroll
            for (int mt = 0; mt < 2; mt++) {
                int row = a_row[mt];
                uint32_t off = (uint32_t)row * 128 +
                               (uint32_t)(((2 * ks + a_ch) ^ (row & 7)) << 4);
                LDSM_X4(ah[mt][0], ah[mt][1], ah[mt][2], ah[mt][3], base + OFF_AH + off);
                LDSM_X4(al[mt][0], al[mt][1], al[mt][2], al[mt][3], base + OFF_AL + off);
            }
            #pragma unroll
            for (int g = 0; g < 4; g++) {
                int row = b_row[g];
                uint32_t off = (uint32_t)row * 128 +
                               (uint32_t)(((2 * ks + b_ch) ^ (row & 7)) << 4);
                uint32_t r0, r1, r2, r3;
                LDSM_X4(r0, r1, r2, r3, base + OFF_WH + off);
                bh[2 * g][0] = r0; bh[2 * g][1] = r1;
                bh[2 * g + 1][0] = r2; bh[2 * g + 1][1] = r3;
                LDSM_X4(r0, r1, r2, r3, base + OFF_WL + off);
                bl[2 * g][0] = r0; bl[2 * g][1] = r1;
                bl[2 * g + 1][0] = r2; bl[2 * g + 1][1] = r3;
            }
            #pragma unroll
            for (int mt = 0; mt < 2; mt++)
                #pragma unroll
                for (int nt = 0; nt < 8; nt++) {
                    mma_bf16(acc[mt][nt], ah[mt], bh[nt]);
                    mma_bf16(acc[mt][nt], ah[mt], bl[nt]);
                    mma_bf16(acc[mt][nt], al[mt], bh[nt]);
                }
        }
        __syncthreads();
    }

    // epilogue
    #pragma unroll
    for (int mt = 0; mt < 2; mt++) {
        int row0 = m0 + wm * 32 + mt * 16 + (l >> 2);
        #pragma unroll
        for (int nt = 0; nt < 8; nt++) {
            int bi = wn * 64 + nt * 8 + (l & 3) * 2;
            int col = n0 + bi;
            float bv0 = s_bias[bi], bv1 = s_bias[bi + 1];
            float v0 = acc[mt][nt][0] + bv0;
            float v1 = acc[mt][nt][1] + bv1;
            float v2 = acc[mt][nt][2] + bv0;
            float v3 = acc[mt][nt][3] + bv1;
            if (RELU) {
                v0 = fmaxf(v0, 0.f); v1 = fmaxf(v1, 0.f);
                v2 = fmaxf(v2, 0.f); v3 = fmaxf(v3, 0.f);
            }
            if (WF32) {
                *(float2*)(Cf32 + (size_t)row0 * HH + col)       = make_float2(v0, v1);
                *(float2*)(Cf32 + (size_t)(row0 + 8) * HH + col) = make_float2(v2, v3);
            }
            if (WHILO) {
                uint32_t hw, lw;
                split_pack(v0, v1, hw, lw);
                *(uint32_t*)(Chi + (size_t)row0 * HH + col) = hw;
                *(uint32_t*)(Clo + (size_t)row0 * HH + col) = lw;
                split_pack(v2, v3, hw, lw);
                *(uint32_t*)(Chi + (size_t)(row0 + 8) * HH + col) = hw;
                *(uint32_t*)(Clo + (size_t)(row0 + 8) * HH + col) = lw;
            }
        }
    }
}

// ---------------- weight hi/lo conversion ------------------------------------
__global__ void cvt_weights(const float* __restrict__ g1w2, const float* __restrict__ g2w1,
                            const float* __restrict__ g2w2, const float* __restrict__ t_in_w,
                            const float* __restrict__ t_out_w, const float* __restrict__ t_ff1_w,
                            const float* __restrict__ t_ff2_w)
{
    int slot = blockIdx.y;
    const float* src;
    switch (slot) {
        case 0: src = g1w2; break;
        case 1: src = g2w1; break;
        case 2: src = g2w2; break;
        case 3: src = t_in_w + 512 * HH; break;
        case 4: src = t_out_w; break;
        case 5: src = t_ff1_w; break;
        case 6: src = t_ff2_w; break;
        case 7: src = t_in_w + 768 * HH + 512 * HH; break;
        case 8: src = t_out_w + HH * HH; break;
        case 9: src = t_ff1_w + HH * HH; break;
        default: src = t_ff2_w + HH * HH; break;
    }
    int i = blockIdx.x * 256 + threadIdx.x;
    float f = src[i];
    __nv_bfloat16 hi = __float2bfloat16(f);
    __nv_bfloat16 lo = __float2bfloat16(f - __bfloat162float(hi));
    g_Whi[(size_t)slot * HH * HH + i] = hi;
    g_Wlo[(size_t)slot * HH * HH + i] = lo;
}

// ---------------- K1: lidar MLP + node assembly ------------------------------
__global__ void lidar_node_kernel(const float* __restrict__ data,
                                  const float* __restrict__ lw1,
                                  const float* __restrict__ lb1,
                                  const float* __restrict__ lw2,
                                  const float* __restrict__ lb2)
{
    int tok = blockIdx.x;
    int t = threadIdx.x;
    __shared__ float s_lidar[20];
    __shared__ float s_lf1[256];
    const float* row = data + (size_t)tok * DNODE;
    if (t < 20) s_lidar[t] = row[18 + t];
    if (t < 18) g_node[(size_t)tok * DNODE + t] = row[t];
    __syncthreads();
    float acc = lb1[t];
    #pragma unroll
    for (int k = 0; k < 20; k++) acc += lw1[t * 20 + k] * s_lidar[k];
    s_lf1[t] = fmaxf(acc, 0.0f);
    __syncthreads();
    int wid = t >> 5, lane = t & 31;
    for (int o = wid; o < 20; o += 8) {
        const float* w = lw2 + o * 256;
        float s = 0.0f;
        #pragma unroll
        for (int k = 0; k < 8; k++) s += s_lf1[lane + 32 * k] * w[lane + 32 * k];
        #pragma unroll
        for (int off = 16; off > 0; off >>= 1) s += __shfl_xor_sync(~0u, s, off);
        if (lane == 0)
            g_node[(size_t)tok * DNODE + 18 + o] = fmaxf(s + lb2[o], 0.0f);
    }
}

// ---------------- column sums -------------------------------------------------
template<int D>
__global__ void colsum_kernel(const float* __restrict__ h, float* __restrict__ S)
{
    int b = blockIdx.x;
    int t = threadIdx.x;
    if (t >= D) return;
    const float* p = h + (size_t)b * NN * D + t;
    float s = 0.0f;
    #pragma unroll 8
    for (int j = 0; j < NN; j++) s += p[(size_t)j * D];
    S[b * D + t] = s;
}

// ---------------- aggregation: colsum + sparse far-pair correction -----------
template<int D, bool HILO>
__global__ void agg_kernel(const float* __restrict__ data,
                           const float* __restrict__ S,
                           const float* __restrict__ h,
                           float* __restrict__ outf,
                           __nv_bfloat16* __restrict__ ohi,
                           __nv_bfloat16* __restrict__ olo)
{
    int b = blockIdx.x;
    int jc = blockIdx.y;
    int tid = threadIdx.x;
    __shared__ float px[NN], py[NN];
    __shared__ float sS[D];
    __shared__ int s_cnt;
    __shared__ short s_list[NN];
    const float* db = data + (size_t)b * NN * DNODE;
    px[tid] = db[(size_t)tid * DNODE + 0];
    py[tid] = db[(size_t)tid * DNODE + 1];
    if (tid < D) sS[tid] = S[b * D + tid];
    __syncthreads();
    for (int jj = 0; jj < 64; jj++) {
        int j = jc * 64 + jj;
        float dx = px[tid] - px[j];
        float dy = py[tid] - py[j];
        bool far = (tid != j) && (sqrtf(dx * dx + dy * dy) > 10.0f);
        if (tid == 0) s_cnt = 0;
        int nf = __syncthreads_count(far);
        float v;
        if (nf == 0) {
            if (tid < D) v = sS[tid];
        } else {
            if (far) { int p = atomicAdd(&s_cnt, 1); s_list[p] = (short)tid; }
            __syncthreads();
            if (tid < D) {
                v = sS[tid];
                for (int l = 0; l < nf; l++)
                    v -= h[((size_t)(b * NN + s_list[l])) * D + tid];
            }
            __syncthreads();
        }
        if (tid < D) {
            size_t o = ((size_t)(b * NN + j)) * D + tid;
            if (HILO) {
                __nv_bfloat16 hi = __float2bfloat16(v);
                ohi[o] = hi;
                olo[o] = __float2bfloat16(v - __bfloat162float(hi));
            } else {
                outf[o] = v;
            }
        }
    }
}

// ---------------- fp32 SGEMM (K=38 first GIN layer) --------------------------
template<bool RELU, bool WF32, bool WHILO>
__global__ __launch_bounds__(256)
void sgemm_t(const float* __restrict__ A, const float* __restrict__ W,
             const float* __restrict__ bias, float* __restrict__ C,
             __nv_bfloat16* __restrict__ Chi, __nv_bfloat16* __restrict__ Clo,
             int M, int N, int K)
{
    constexpr int BM = 128, BK = 16, LD = BM + 4;
    __shared__ float As[BK][LD];
    __shared__ float Bs[BK][LD];
    int m0 = blockIdx.y * BM, n0 = blockIdx.x * 128;
    int tid = threadIdx.x;
    int tx = tid & 15, ty = tid >> 4;
    int lr = tid >> 1;
    int lk = (tid & 1) * 8;

    float acc[8][8];
    #pragma unroll
    for (int i = 0; i < 8; i++)
        #pragma unroll
        for (int j = 0; j < 8; j++) acc[i][j] = 0.0f;

    const float* ap = A + (size_t)(m0 + lr) * K + lk;
    const float* wp = W + (size_t)(n0 + lr) * K + lk;

    for (int k0 = 0; k0 < K; k0 += BK) {
        #pragma unroll
        for (int u = 0; u < 8; u++) {
            int kk = k0 + lk + u;
            As[lk + u][lr] = (kk < K) ? ap[k0 + u] : 0.0f;
            Bs[lk + u][lr] = (kk < K) ? wp[k0 + u] : 0.0f;
        }
        __syncthreads();
        #pragma unroll
        for (int k = 0; k < BK; k++) {
            float a[8], b[8];
            *(float4*)&a[0] = *(const float4*)&As[k][ty * 4];
            *(float4*)&a[4] = *(const float4*)&As[k][64 + ty * 4];
            *(float4*)&b[0] = *(const float4*)&Bs[k][tx * 4];
            *(float4*)&b[4] = *(const float4*)&Bs[k][64 + tx * 4];
            #pragma unroll
            for (int i = 0; i < 8; i++)
                #pragma unroll
                for (int j = 0; j < 8; j++)
                    acc[i][j] += a[i] * b[j];
        }
        __syncthreads();
    }

    float bv[8];
    #pragma unroll
    for (int j = 0; j < 8; j++) {
        int c = (j < 4) ? (tx * 4 + j) : (64 + tx * 4 + j - 4);
        bv[j] = bias[n0 + c];
    }
    #pragma unroll
    for (int i = 0; i < 8; i++) {
        int r = m0 + ((i < 4) ? (ty * 4 + i) : (64 + ty * 4 + i - 4));
        #pragma unroll
        for (int half = 0; half < 2; half++) {
            int cbase = n0 + ((half == 0) ? tx * 4 : 64 + tx * 4);
            float vv[4];
            #pragma unroll
            for (int j = 0; j < 4; j++) {
                float f = acc[i][half * 4 + j] + bv[half * 4 + j];
                vv[j] = RELU ? fmaxf(f, 0.0f) : f;
            }
            if (WF32)
                *(float4*)(C + (size_t)r * N + cbase) = *(float4*)vv;
            if (WHILO) {
                uint32_t hw[2], lw[2];
                split_pack(vv[0], vv[1], hw[0], lw[0]);
                split_pack(vv[2], vv[3], hw[1], lw[1]);
                *(uint2*)(Chi + (size_t)r * N + cbase) = *(uint2*)hw;
                *(uint2*)(Clo + (size_t)r * N + cbase) = *(uint2*)lw;
            }
        }
    }
}

// ---------------- LN: out = LN(x+y)*g + b (+ hi/lo) ---------------------------
__global__ void ln_kernel(const float* __restrict__ x, const float* __restrict__ y,
                          const float* __restrict__ g, const float* __restrict__ b,
                          float* __restrict__ out,
                          __nv_bfloat16* __restrict__ ohi, __nv_bfloat16* __restrict__ olo)
{
    int tok = blockIdx.x, t = threadIdx.x;
    size_t base = (size_t)tok * HH;
    float v = x[base + t] + y[base + t];
    __shared__ float red1[8], red2[8];
    float s = v;
    #pragma unroll
    for (int o = 16; o > 0; o >>= 1) s += __shfl_xor_sync(~0u, s, o);
    if ((t & 31) == 0) red1[t >> 5] = s;
    __syncthreads();
    float tot = 0.0f;
    #pragma unroll
    for (int w = 0; w < 8; w++) tot += red1[w];
    float mean = tot * (1.0f / 256.0f);
    float d = v - mean;
    float s2 = d * d;
    #pragma unroll
    for (int o = 16; o > 0; o >>= 1) s2 += __shfl_xor_sync(~0u, s2, o);
    if ((t & 31) == 0) red2[t >> 5] = s2;
    __syncthreads();
    float tot2 = 0.0f;
    #pragma unroll
    for (int w = 0; w < 8; w++) tot2 += red2[w];
    float var = tot2 * (1.0f / 256.0f);
    float r = d / sqrtf(var + 1e-5f) * g[t] + b[t];
    out[base + t] = r;
    __nv_bfloat16 hi = __float2bfloat16(r);
    ohi[base + t] = hi;
    olo[base + t] = __float2bfloat16(r - __bfloat162float(hi));
}

// ---------------- final head --------------------------------------------------
__global__ void fc_kernel(const float* __restrict__ h, const float* __restrict__ W,
                          const float* __restrict__ bias, float* __restrict__ out)
{
    int tok = blockIdx.x;
    int w = threadIdx.x >> 5, lane = threadIdx.x & 31;
    const float* hr = h + (size_t)tok * HH;
    const float* wr = W + w * HH;
    float s = 0.0f;
    #pragma unroll
    for (int k = 0; k < 8; k++) s += hr[lane + 32 * k] * wr[lane + 32 * k];
    #pragma unroll
    for (int o = 16; o > 0; o >>= 1) s += __shfl_xor_sync(~0u, s, o);
    if (lane == 0) out[(size_t)tok * 5 + w] = s + bias[w];
}

// ---------------- launch ------------------------------------------------------
extern "C" void kernel_launch(void* const* d_in, const int* in_sizes, int n_in,
                              void* d_out, int out_size)
{
    const float* data   = (const float*)d_in[0];
    const float* lw1    = (const float*)d_in[1];
    const float* lb1    = (const float*)d_in[2];
    const float* lw2    = (const float*)d_in[3];
    const float* lb2    = (const float*)d_in[4];
    const float* g1w1   = (const float*)d_in[5];
    const float* g1b1   = (const float*)d_in[6];
    const float* g1w2   = (const float*)d_in[7];
    const float* g1b2   = (const float*)d_in[8];
    const float* g2w1   = (const float*)d_in[9];
    const float* g2b1   = (const float*)d_in[10];
    const float* g2w2   = (const float*)d_in[11];
    const float* g2b2   = (const float*)d_in[12];
    const float* t_in_w = (const float*)d_in[13];
    const float* t_in_b = (const float*)d_in[14];
    const float* t_out_w= (const float*)d_in[15];
    const float* t_out_b= (const float*)d_in[16];
    const float* t_ln1_g= (const float*)d_in[17];
    const float* t_ln1_b= (const float*)d_in[18];
    const float* t_ff1_w= (const float*)d_in[19];
    const float* t_ff1_b= (const float*)d_in[20];
    const float* t_ff2_w= (const float*)d_in[21];
    const float* t_ff2_b= (const float*)d_in[22];
    const float* t_ln2_g= (const float*)d_in[23];
    const float* t_ln2_b= (const float*)d_in[24];
    const float* fc_w   = (const float*)d_in[25];
    const float* fc_b   = (const float*)d_in[26];
    float* out = (float*)d_out;

    float *node, *bufA, *bufB, *bufC, *S;
    __nv_bfloat16 *h0hi, *h0lo, *h1hi, *h1lo, *Whi, *Wlo;
    cudaGetSymbolAddress((void**)&node, g_node);
    cudaGetSymbolAddress((void**)&bufA, g_bufA);
    cudaGetSymbolAddress((void**)&bufB, g_bufB);
    cudaGetSymbolAddress((void**)&bufC, g_bufC);
    cudaGetSymbolAddress((void**)&S,    g_S);
    cudaGetSymbolAddress((void**)&h0hi, g_h0hi);
    cudaGetSymbolAddress((void**)&h0lo, g_h0lo);
    cudaGetSymbolAddress((void**)&h1hi, g_h1hi);
    cudaGetSymbolAddress((void**)&h1lo, g_h1lo);
    cudaGetSymbolAddress((void**)&Whi,  g_Whi);
    cudaGetSymbolAddress((void**)&Wlo,  g_Wlo);

    const int SMEM_DYN = 2 * 64 * 1024;
    cudaFuncSetAttribute(mgemm<true,  true,  false>, cudaFuncAttributeMaxDynamicSharedMemorySize, SMEM_DYN);
    cudaFuncSetAttribute(mgemm<true,  false, true >, cudaFuncAttributeMaxDynamicSharedMemorySize, SMEM_DYN);
    cudaFuncSetAttribute(mgemm<true,  true,  true >, cudaFuncAttributeMaxDynamicSharedMemorySize, SMEM_DYN);
    cudaFuncSetAttribute(mgemm<false, false, true >, cudaFuncAttributeMaxDynamicSharedMemorySize, SMEM_DYN);
    cudaFuncSetAttribute(mgemm<false, true,  false>, cudaFuncAttributeMaxDynamicSharedMemorySize, SMEM_DYN);

    #define WSLOT(i) (Whi + (size_t)(i) * HH * HH), (Wlo + (size_t)(i) * HH * HH)

    dim3 gridA(BATCH, 8, 1);
    dim3 gridS(2, TOKENS / 128, 1);
    dim3 gridM(2, TOKENS / 128, 1);

    // weight conversion
    cvt_weights<<<dim3(256, NWSLOT, 1), 256>>>(g1w2, g2w1, g2w2, t_in_w, t_out_w, t_ff1_w, t_ff2_w);
    // 1. lidar MLP -> node
    lidar_node_kernel<<<TOKENS, 256>>>(data, lw1, lb1, lw2, lb2);
    // 2. agg0 (fp32) -> bufA
    colsum_kernel<DNODE><<<BATCH, 256>>>(node, S);
    agg_kernel<DNODE, false><<<gridA, NN>>>(data, S, node, bufA, nullptr, nullptr);
    // 3. GIN1 layer 1 (K=38, fp32 FFMA) -> h0 hi/lo
    sgemm_t<true, false, true><<<gridS, 256>>>(bufA, g1w1, g1b1, nullptr, h0hi, h0lo, TOKENS, HH, DNODE);
    // 4. GIN1 layer 2 (HMMA) -> bufC fp32
    mgemm<true, true, false><<<gridM, 256, SMEM_DYN>>>(h0hi, h0lo, WSLOT(0), g1b2, bufC, nullptr, nullptr);
    // 5. agg1 -> h0 hi/lo
    colsum_kernel<HH><<<BATCH, 256>>>(bufC, S);
    agg_kernel<HH, true><<<gridA, NN>>>(data, S, bufC, nullptr, h0hi, h0lo);
    // 6. GIN2
    mgemm<true, false, true><<<gridM, 256, SMEM_DYN>>>(h0hi, h0lo, WSLOT(1), g2b1, nullptr, h1hi, h1lo);
    mgemm<true, true, true><<<gridM, 256, SMEM_DYN>>>(h1hi, h1lo, WSLOT(2), g2b2, bufC, h0hi, h0lo);
    // 7. transformer layers: h fp32 in bufC, h hi/lo in h0
    for (int l = 0; l < 2; l++) {
        const float* bv  = t_in_b + (size_t)l * 768 + 512;
        const float* bo  = t_out_b + (size_t)l * HH;
        const float* l1g = t_ln1_g + (size_t)l * HH;
        const float* l1b = t_ln1_b + (size_t)l * HH;
        const float* b1  = t_ff1_b + (size_t)l * HH;
        const float* b2  = t_ff2_b + (size_t)l * HH;
        const float* l2g = t_ln2_g + (size_t)l * HH;
        const float* l2b = t_ln2_b + (size_t)l * HH;

        // v = h @ Wv^T + bv -> h1 hi/lo
        mgemm<false, false, true><<<gridM, 256, SMEM_DYN>>>(h0hi, h0lo, WSLOT(3 + l * 4), bv, nullptr, h1hi, h1lo);
        // attn = v @ Wo^T + bo -> bufB fp32
        mgemm<false, true, false><<<gridM, 256, SMEM_DYN>>>(h1hi, h1lo, WSLOT(4 + l * 4), bo, bufB, nullptr, nullptr);
        // h = LN(h + attn) -> bufA fp32 + h0 hi/lo
        ln_kernel<<<TOKENS, 256>>>(bufC, bufB, l1g, l1b, bufA, h0hi, h0lo);
        // ff1 = relu(h @ W1^T + b1) -> h1 hi/lo
        mgemm<true, false, true><<<gridM, 256, SMEM_DYN>>>(h0hi, h0lo, WSLOT(5 + l * 4), b1, nullptr, h1hi, h1lo);
        // ff2 = ff1 @ W2^T + b2 -> bufB fp32
        mgemm<false, true, false><<<gridM, 256, SMEM_DYN>>>(h1hi, h1lo, WSLOT(6 + l * 4), b2, bufB, nullptr, nullptr);
        // h = LN(h + ff2) -> bufC fp32 + h0 hi/lo
        ln_kernel<<<TOKENS, 256>>>(bufA, bufB, l2g, l2b, bufC, h0hi, h0lo);
    }
    // 8. head
    fc_kernel<<<TOKENS, 160>>>(bufC, fc_w, fc_b, out);
    (void)in_sizes; (void)n_in; (void)out_size;
}

// round 5
// speedup vs baseline: 12.0901x; 4.1081x over previous
#include <cuda_runtime.h>
#include <math.h>
#include <stdint.h>

#define BATCH 64
#define NN    512
#define HH    256
#define DNODE 38
#define TOKENS (BATCH*NN)
#define MAXW  (64 + TOKENS)

// ---------------- scratch (device globals) ----------------------------------
__device__ float g_node[TOKENS * DNODE];
__device__ float g_wA38[(size_t)MAXW * DNODE];
__device__ float g_bufA[(size_t)MAXW * HH];
__device__ float g_bufB[(size_t)MAXW * HH];
__device__ float g_bufC[(size_t)MAXW * HH];
__device__ float g_bufD[(size_t)MAXW * HH];
__device__ float g_S0[BATCH * DNODE];
__device__ float g_S1[BATCH * HH];
__device__ float g_outw[(size_t)MAXW * 5];
__device__ unsigned g_farmask[(size_t)TOKENS * 16];
__device__ int g_dirtyList[TOKENS];
__device__ int g_slot[TOKENS];
__device__ int g_ndB[BATCH];
__device__ int g_nDirty;
__device__ int g_nWork;

// ---------------- init -------------------------------------------------------
__global__ void init_kernel()
{
    int i = blockIdx.x * 256 + threadIdx.x;
    if (i < TOKENS) g_slot[i] = -1;
    if (i == 0) g_nDirty = 0;
    if (i < BATCH) g_ndB[i] = 0;
}
__global__ void finalize_kernel() { g_nWork = 64 + g_nDirty; }

// ---------------- lidar MLP + node assembly (8 tokens / block) ---------------
__global__ __launch_bounds__(256)
void lidar8_kernel(const float* __restrict__ data,
                   const float* __restrict__ lw1, const float* __restrict__ lb1,
                   const float* __restrict__ lw2, const float* __restrict__ lb2)
{
    __shared__ float s_w1t[20 * 256];   // transposed lw1: [k][h]
    __shared__ float s_lid[8][20];
    __shared__ float s_hid[8][256];
    int tid = threadIdx.x;
    int tok0 = blockIdx.x * 8;

    for (int idx = tid; idx < 20 * 256; idx += 256) {
        int h = idx / 20, k = idx % 20;
        s_w1t[k * 256 + h] = lw1[h * 20 + k];
    }
    if (tid < 160) {
        int t = tid / 20, c = tid % 20;
        s_lid[t][c] = data[(size_t)(tok0 + t) * DNODE + 18 + c];
    }
    // copy orig 18 features straight through
    for (int idx = tid; idx < 8 * 18; idx += 256) {
        int t = idx / 18, c = idx % 18;
        g_node[(size_t)(tok0 + t) * DNODE + c] = data[(size_t)(tok0 + t) * DNODE + c];
    }
    __syncthreads();

    float b1v = lb1[tid];
    #pragma unroll
    for (int t = 0; t < 8; t++) {
        float acc = b1v;
        #pragma unroll
        for (int k = 0; k < 20; k++) acc += s_w1t[k * 256 + tid] * s_lid[t][k];
        s_hid[t][tid] = fmaxf(acc, 0.0f);
    }
    __syncthreads();

    int w = tid >> 5, lane = tid & 31;     // warp w handles token w
    const float* hid = s_hid[w];
    for (int o = 0; o < 20; o++) {
        const float* wr = lw2 + o * 256;
        float s = 0.0f;
        #pragma unroll
        for (int q = 0; q < 8; q++) s += hid[lane + 32 * q] * wr[lane + 32 * q];
        #pragma unroll
        for (int off = 16; off > 0; off >>= 1) s += __shfl_xor_sync(~0u, s, off);
        if (lane == 0)
            g_node[(size_t)(tok0 + w) * DNODE + 18 + o] = fmaxf(s + lb2[o], 0.0f);
    }
}

// ---------------- far-pair detection (mask complement) -----------------------
// far(i,j) = (i!=j) && !(dist<=10); symmetric => every far-neighbor is dirty
__global__ __launch_bounds__(512)
void far_detect_kernel(const float* __restrict__ data)
{
    int b = blockIdx.x;
    int tid = threadIdx.x, w = tid >> 5, lane = tid & 31;
    __shared__ float px[NN], py[NN];
    const float* db = data + (size_t)b * NN * DNODE;
    px[tid] = db[(size_t)tid * DNODE + 0];
    py[tid] = db[(size_t)tid * DNODE + 1];
    __syncthreads();
    for (int jj = 0; jj < 32; jj++) {
        int j = w * 32 + jj;
        float xj = px[j], yj = py[j];
        unsigned any = 0;
        #pragma unroll
        for (int wd = 0; wd < 16; wd++) {
            int i = wd * 32 + lane;
            float dx = px[i] - xj, dy = py[i] - yj;
            bool far = (i != j) && !(sqrtf(dx * dx + dy * dy) <= 10.0f);
            unsigned m = __ballot_sync(~0u, far);
            if (lane == 0) g_farmask[((size_t)(b * NN + j)) * 16 + wd] = m;
            any |= m;
        }
        if (lane == 0 && any) {
            int idx = atomicAdd(&g_nDirty, 1);
            g_dirtyList[idx] = b * NN + j;
            g_slot[b * NN + j] = 64 + idx;
            atomicAdd(&g_ndB[b], 1);
        }
    }
}

// ---------------- column sums -------------------------------------------------
template<int D>
__global__ void colsum_kernel(const float* __restrict__ h, float* __restrict__ S)
{
    int b = blockIdx.x;
    int t = threadIdx.x;
    if (t >= D) return;
    const float* p = h + (size_t)b * NN * D + t;
    float s = 0.0f;
    #pragma unroll 8
    for (int j = 0; j < NN; j++) s += p[(size_t)j * D];
    S[b * D + t] = s;
}

// ---------------- build agg0 work rows ---------------------------------------
__global__ __launch_bounds__(64)
void build_work0_kernel()
{
    int nW = g_nWork;
    int t = threadIdx.x;
    for (int w = blockIdx.x; w < nW; w += gridDim.x) {
        float v = 0.0f;
        if (w < 64) {
            if (t < DNODE) v = g_S0[w * DNODE + t];
        } else {
            int tok = g_dirtyList[w - 64];
            int b = tok >> 9;
            if (t < DNODE) v = g_S0[b * DNODE + t];
            for (int wd = 0; wd < 16; wd++) {
                unsigned m = g_farmask[(size_t)tok * 16 + wd];
                while (m) {
                    int i = wd * 32 + __ffs(m) - 1; m &= m - 1;
                    if (t < DNODE)
                        v -= g_node[((size_t)(b * NN) + i) * DNODE + t];
                }
            }
        }
        if (t < DNODE) g_wA38[(size_t)w * DNODE + t] = v;
    }
}

// ---------------- S1 = (512-nd)*u1 + sum(dirty h1) ----------------------------
__global__ void reduce_S1_kernel(const float* __restrict__ h1)
{
    int b = blockIdx.x, t = threadIdx.x;
    float u = h1[(size_t)b * HH + t];
    int nd = g_ndB[b];
    float s = (float)(NN - nd) * u;
    int nD = g_nDirty;
    for (int e = 0; e < nD; e++) {
        int tok = g_dirtyList[e];
        if ((tok >> 9) == b) s += h1[(size_t)(64 + e) * HH + t];
    }
    g_S1[b * HH + t] = s;
}

// ---------------- build agg1 work rows ---------------------------------------
__global__ __launch_bounds__(256)
void build_agg1_kernel(const float* __restrict__ h1, float* __restrict__ out)
{
    int nW = g_nWork;
    int t = threadIdx.x;
    for (int w = blockIdx.x; w < nW; w += gridDim.x) {
        float v;
        if (w < 64) {
            v = g_S1[w * HH + t];
        } else {
            int tok = g_dirtyList[w - 64];
            int b = tok >> 9;
            v = g_S1[b * HH + t];
            for (int wd = 0; wd < 16; wd++) {
                unsigned m = g_farmask[(size_t)tok * 16 + wd];
                while (m) {
                    int i = wd * 32 + __ffs(m) - 1; m &= m - 1;
                    int sl = g_slot[b * NN + i];   // far neighbor is dirty
                    v -= h1[(size_t)sl * HH + t];
                }
            }
        }
        out[(size_t)w * HH + t] = v;
    }
}

// ---------------- small fp32 GEMM over work rows ------------------------------
// C[w, n] = act( A[w,:K] . W[n,:K] + bias[n] ),  w < g_nWork, n < 256
// block = 16w x 16n, K staged in 64-chunks
template<bool RELU>
__global__ __launch_bounds__(256)
void small_gemm(const float* __restrict__ A, const float* __restrict__ W,
                const float* __restrict__ bias, float* __restrict__ C, int K)
{
    __shared__ float As[16][65];
    __shared__ float Ws[16][65];
    int nW = g_nWork;
    int tid = threadIdx.x;
    int tx = tid & 15, ty = tid >> 4;
    int n0 = blockIdx.x * 16;

    for (int wt = blockIdx.y; wt * 16 < nW; wt += gridDim.y) {
        int w0 = wt * 16;
        float acc = 0.0f;
        for (int k0 = 0; k0 < K; k0 += 64) {
            #pragma unroll
            for (int u = tid; u < 16 * 64; u += 256) {
                int r = u >> 6, c = u & 63;
                int k = k0 + c;
                float va = 0.0f, vw = 0.0f;
                if (k < K) {
                    int wrow = w0 + r;
                    if (wrow < nW) va = A[(size_t)wrow * K + k];
                    vw = W[(size_t)(n0 + r) * K + k];
                }
                As[r][c] = va;
                Ws[r][c] = vw;
            }
            __syncthreads();
            #pragma unroll 16
            for (int k = 0; k < 64; k++)
                acc += As[ty][k] * Ws[tx][k];
            __syncthreads();
        }
        int w = w0 + ty;
        if (w < nW) {
            float v = acc + bias[n0 + tx];
            if (RELU) v = fmaxf(v, 0.0f);
            C[(size_t)w * HH + n0 + tx] = v;
        }
    }
}

// ---------------- LN over work rows: out = LN(x+y)*g + b ---------------------
__global__ __launch_bounds__(256)
void ln_kernel(const float* __restrict__ x, const float* __restrict__ y,
               const float* __restrict__ g, const float* __restrict__ b,
               float* __restrict__ out)
{
    int nW = g_nWork;
    int t = threadIdx.x;
    __shared__ float red1[8], red2[8];
    for (int row = blockIdx.x; row < nW; row += gridDim.x) {
        size_t base = (size_t)row * HH;
        float v = x[base + t] + y[base + t];
        float s = v;
        #pragma unroll
        for (int o = 16; o > 0; o >>= 1) s += __shfl_xor_sync(~0u, s, o);
        if ((t & 31) == 0) red1[t >> 5] = s;
        __syncthreads();
        float tot = 0.0f;
        #pragma unroll
        for (int w = 0; w < 8; w++) tot += red1[w];
        float mean = tot * (1.0f / 256.0f);
        float d = v - mean;
        float s2 = d * d;
        #pragma unroll
        for (int o = 16; o > 0; o >>= 1) s2 += __shfl_xor_sync(~0u, s2, o);
        if ((t & 31) == 0) red2[t >> 5] = s2;
        __syncthreads();
        float tot2 = 0.0f;
        #pragma unroll
        for (int w = 0; w < 8; w++) tot2 += red2[w];
        float var = tot2 * (1.0f / 256.0f);
        out[base + t] = d / sqrtf(var + 1e-5f) * g[t] + b[t];
    }
}

// ---------------- head on work rows ------------------------------------------
__global__ __launch_bounds__(160)
void fc_work_kernel(const float* __restrict__ h, const float* __restrict__ W,
                    const float* __restrict__ bias)
{
    int nW = g_nWork;
    int o = threadIdx.x >> 5, lane = threadIdx.x & 31;
    const float* wr = W + o * HH;
    for (int w = blockIdx.x; w < nW; w += gridDim.x) {
        const float* hr = h + (size_t)w * HH;
        float s = 0.0f;
        #pragma unroll
        for (int k = 0; k < 8; k++) s += hr[lane + 32 * k] * wr[lane + 32 * k];
        #pragma unroll
        for (int off = 16; off > 0; off >>= 1) s += __shfl_xor_sync(~0u, s, off);
        if (lane == 0) g_outw[(size_t)w * 5 + o] = s + bias[o];
    }
}

// ---------------- scatter to tokens ------------------------------------------
__global__ void scatter_kernel(float* __restrict__ out)
{
    int tok = blockIdx.x * 256 + threadIdx.x;
    if (tok >= TOKENS) return;
    int slot = g_slot[tok];
    int row = (slot < 0) ? (tok >> 9) : slot;
    #pragma unroll
    for (int k = 0; k < 5; k++)
        out[(size_t)tok * 5 + k] = g_outw[(size_t)row * 5 + k];
}

// ---------------- launch ------------------------------------------------------
extern "C" void kernel_launch(void* const* d_in, const int* in_sizes, int n_in,
                              void* d_out, int out_size)
{
    const float* data   = (const float*)d_in[0];
    const float* lw1    = (const float*)d_in[1];
    const float* lb1    = (const float*)d_in[2];
    const float* lw2    = (const float*)d_in[3];
    const float* lb2    = (const float*)d_in[4];
    const float* g1w1   = (const float*)d_in[5];
    const float* g1b1   = (const float*)d_in[6];
    const float* g1w2   = (const float*)d_in[7];
    const float* g1b2   = (const float*)d_in[8];
    const float* g2w1   = (const float*)d_in[9];
    const float* g2b1   = (const float*)d_in[10];
    const float* g2w2   = (const float*)d_in[11];
    const float* g2b2   = (const float*)d_in[12];
    const float* t_in_w = (const float*)d_in[13];
    const float* t_in_b = (const float*)d_in[14];
    const float* t_out_w= (const float*)d_in[15];
    const float* t_out_b= (const float*)d_in[16];
    const float* t_ln1_g= (const float*)d_in[17];
    const float* t_ln1_b= (const float*)d_in[18];
    const float* t_ff1_w= (const float*)d_in[19];
    const float* t_ff1_b= (const float*)d_in[20];
    const float* t_ff2_w= (const float*)d_in[21];
    const float* t_ff2_b= (const float*)d_in[22];
    const float* t_ln2_g= (const float*)d_in[23];
    const float* t_ln2_b= (const float*)d_in[24];
    const float* fc_w   = (const float*)d_in[25];
    const float* fc_b   = (const float*)d_in[26];
    float* out = (float*)d_out;

    float *node, *wA38, *bufA, *bufB, *bufC, *bufD, *S0;
    cudaGetSymbolAddress((void**)&node, g_node);
    cudaGetSymbolAddress((void**)&wA38, g_wA38);
    cudaGetSymbolAddress((void**)&bufA, g_bufA);
    cudaGetSymbolAddress((void**)&bufB, g_bufB);
    cudaGetSymbolAddress((void**)&bufC, g_bufC);
    cudaGetSymbolAddress((void**)&bufD, g_bufD);
    cudaGetSymbolAddress((void**)&S0,   g_S0);

    dim3 gridSG(16, 32, 1);

    // 0. reset per-call state
    init_kernel<<<TOKENS / 256, 256>>>();
    // 1. node features
    lidar8_kernel<<<TOKENS / 8, 256>>>(data, lw1, lb1, lw2, lb2);
    // 2. far-pair structure (dirty set)
    far_detect_kernel<<<BATCH, NN>>>(data);
    finalize_kernel<<<1, 1>>>();
    // 3. S0 = colsum(node); build agg0 work rows
    colsum_kernel<DNODE><<<BATCH, 256>>>(node, S0);
    build_work0_kernel<<<256, 64>>>();
    // 4. GIN1 on work rows
    small_gemm<true><<<gridSG, 256>>>(wA38, g1w1, g1b1, bufB, DNODE);
    small_gemm<true><<<gridSG, 256>>>(bufB, g1w2, g1b2, bufC, HH);
    // 5. agg1: S1 then work rows
    reduce_S1_kernel<<<BATCH, 256>>>(bufC);
    build_agg1_kernel<<<256, 256>>>(bufC, bufA);
    // 6. GIN2
    small_gemm<true><<<gridSG, 256>>>(bufA, g2w1, g2b1, bufB, HH);
    small_gemm<true><<<gridSG, 256>>>(bufB, g2w2, g2b2, bufC, HH);
    // 7. transformer layers (h in bufC)
    for (int l = 0; l < 2; l++) {
        const float* Wv  = t_in_w + (size_t)l * 768 * HH + (size_t)512 * HH;
        const float* bv  = t_in_b + (size_t)l * 768 + 512;
        const float* Wo  = t_out_w + (size_t)l * HH * HH;
        const float* bo  = t_out_b + (size_t)l * HH;
        const float* l1g = t_ln1_g + (size_t)l * HH;
        const float* l1b = t_ln1_b + (size_t)l * HH;
        const float* W1  = t_ff1_w + (size_t)l * HH * HH;
        const float* b1  = t_ff1_b + (size_t)l * HH;
        const float* W2  = t_ff2_w + (size_t)l * HH * HH;
        const float* b2  = t_ff2_b + (size_t)l * HH;
        const float* l2g = t_ln2_g + (size_t)l * HH;
        const float* l2b = t_ln2_b + (size_t)l * HH;

        small_gemm<false><<<gridSG, 256>>>(bufC, Wv, bv, bufA, HH);   // v
        small_gemm<false><<<gridSG, 256>>>(bufA, Wo, bo, bufD, HH);   // attn
        ln_kernel<<<256, 256>>>(bufC, bufD, l1g, l1b, bufA);          // h'
        small_gemm<true ><<<gridSG, 256>>>(bufA, W1, b1, bufB, HH);   // ff1
        small_gemm<false><<<gridSG, 256>>>(bufB, W2, b2, bufD, HH);   // ff2
        ln_kernel<<<256, 256>>>(bufA, bufD, l2g, l2b, bufC);          // h''
    }
    // 8. head on work rows + scatter to all tokens
    fc_work_kernel<<<64, 160>>>(bufC, fc_w, fc_b);
    scatter_kernel<<<TOKENS / 256, 256>>>(out);
    (void)in_sizes; (void)n_in; (void)out_size;
}

// round 6
// speedup vs baseline: 15.2733x; 1.2633x over previous
#include <cuda_runtime.h>
#include <math.h>
#include <stdint.h>

#define BATCH 64
#define NN    512
#define HH    256
#define DNODE 38
#define TOKENS (BATCH*NN)
#define MAXW  (64 + TOKENS)

// ---------------- scratch (device globals) ----------------------------------
__device__ float g_node[(size_t)TOKENS * DNODE];
__device__ float g_S0[BATCH * DNODE];
__device__ float g_S1[BATCH * HH];
__device__ float g_h1[(size_t)MAXW * HH];
__device__ unsigned g_farmask[(size_t)TOKENS * 16];
__device__ int g_dirtyList[TOKENS];
__device__ int g_slot[TOKENS];
__device__ int g_ndB[BATCH];
__device__ int g_nDirty;

// ---------------- K0: per-call state reset -----------------------------------
__global__ void init_kernel()
{
    int i = blockIdx.x * 256 + threadIdx.x;      // grid 128 -> 32768 threads
    if (i < TOKENS) g_slot[i] = -1;
    if (i < BATCH * DNODE) g_S0[i] = 0.0f;
    if (i < BATCH) g_ndB[i] = 0;
    if (i == 0) g_nDirty = 0;
}

// ---------------- K1: lidar MLP + node assembly + fused colsum(S0) -----------
// 32 tokens per block (all within one batch: 512 % 32 == 0)
__global__ __launch_bounds__(256)
void lidar32_kernel(const float* __restrict__ data,
                    const float* __restrict__ lw1, const float* __restrict__ lb1,
                    const float* __restrict__ lw2, const float* __restrict__ lb2)
{
    __shared__ float s_lid[32][20];
    __shared__ float s_hid[32][256];
    __shared__ float s_node[32][38];
    int tid = threadIdx.x;
    int tok0 = blockIdx.x * 32;

    for (int idx = tid; idx < 32 * 20; idx += 256) {
        int t = idx / 20, c = idx % 20;
        s_lid[t][c] = data[(size_t)(tok0 + t) * DNODE + 18 + c];
    }
    for (int idx = tid; idx < 32 * 18; idx += 256) {
        int t = idx / 18, c = idx % 18;
        s_node[t][c] = data[(size_t)(tok0 + t) * DNODE + c];
    }
    float wreg[20];
    #pragma unroll
    for (int k = 0; k < 20; k++) wreg[k] = lw1[tid * 20 + k];
    float b1v = lb1[tid];
    __syncthreads();

    #pragma unroll 4
    for (int t = 0; t < 32; t++) {
        float acc = b1v;
        #pragma unroll
        for (int k = 0; k < 20; k++) acc += wreg[k] * s_lid[t][k];
        s_hid[t][tid] = fmaxf(acc, 0.0f);
    }
    __syncthreads();

    int w = tid >> 5, lane = tid & 31;
    #pragma unroll
    for (int tt = 0; tt < 4; tt++) {
        int t = w * 4 + tt;
        for (int o = 0; o < 20; o++) {
            const float* wr = lw2 + o * 256;
            float s = 0.0f;
            #pragma unroll
            for (int q = 0; q < 8; q++) s += s_hid[t][lane + 32 * q] * wr[lane + 32 * q];
            #pragma unroll
            for (int off = 16; off; off >>= 1) s += __shfl_xor_sync(~0u, s, off);
            if (!lane) s_node[t][18 + o] = fmaxf(s + lb2[o], 0.0f);
        }
    }
    __syncthreads();

    for (int idx = tid; idx < 32 * 38; idx += 256) {
        int t = idx / 38, c = idx % 38;
        g_node[(size_t)(tok0 + t) * DNODE + c] = s_node[t][c];
    }
    if (tid < 38) {
        float s = 0.0f;
        #pragma unroll 8
        for (int t = 0; t < 32; t++) s += s_node[t][tid];
        atomicAdd(&g_S0[(tok0 >> 9) * DNODE + tid], s);
    }
}

// ---------------- K2: far-pair detection (mask complement, symmetric) --------
__global__ __launch_bounds__(512)
void far_detect_kernel(const float* __restrict__ data)
{
    int b = blockIdx.x;
    int tid = threadIdx.x, w = tid >> 5, lane = tid & 31;
    __shared__ float px[NN], py[NN];
    const float* db = data + (size_t)b * NN * DNODE;
    px[tid] = db[(size_t)tid * DNODE + 0];
    py[tid] = db[(size_t)tid * DNODE + 1];
    __syncthreads();
    for (int jj = 0; jj < 32; jj++) {
        int j = w * 32 + jj;
        float xj = px[j], yj = py[j];
        unsigned any = 0;
        #pragma unroll
        for (int wd = 0; wd < 16; wd++) {
            int i = wd * 32 + lane;
            float dx = px[i] - xj, dy = py[i] - yj;
            float d2 = dx * dx + dy * dy;
            bool near_ = d2 <= 100.0f;
            if (d2 > 99.0f && d2 < 101.0f)      // exact match to ref's sqrt<=10 at boundary
                near_ = (sqrtf(d2) <= 10.0f);
            bool far = (i != j) && !near_;
            unsigned m = __ballot_sync(~0u, far);
            if (!lane) g_farmask[((size_t)(b * NN + j)) * 16 + wd] = m;
            any |= m;
        }
        if (!lane && any) {
            int idx = atomicAdd(&g_nDirty, 1);
            g_dirtyList[idx] = b * NN + j;
            g_slot[b * NN + j] = 64 + idx;
            atomicAdd(&g_ndB[b], 1);
        }
    }
}

// ---------------- K3: work rows -> GIN1 (agg0 build + 2 GEMV layers) ---------
__global__ __launch_bounds__(256)
void gin1_kernel(const float* __restrict__ g1w1, const float* __restrict__ g1b1,
                 const float* __restrict__ g1w2, const float* __restrict__ g1b2)
{
    __shared__ __align__(16) float x38[40];
    __shared__ __align__(16) float y[256];
    int tid = threadIdx.x;
    int nW = 64 + g_nDirty;
    for (int row = blockIdx.x; row < nW; row += gridDim.x) {
        if (tid < DNODE) {
            float v;
            if (row < 64) {
                v = g_S0[row * DNODE + tid];
            } else {
                int tok = g_dirtyList[row - 64];
                int b = tok >> 9;
                v = g_S0[b * DNODE + tid];
                for (int wd = 0; wd < 16; wd++) {
                    unsigned m = g_farmask[(size_t)tok * 16 + wd];
                    while (m) {
                        int i = wd * 32 + __ffs(m) - 1; m &= m - 1;
                        v -= g_node[((size_t)b * NN + i) * DNODE + tid];
                    }
                }
            }
            x38[tid] = v;
        }
        __syncthreads();
        float acc = g1b1[tid];
        #pragma unroll
        for (int k = 0; k < DNODE; k++) acc += x38[k] * g1w1[tid * DNODE + k];
        y[tid] = fmaxf(acc, 0.0f);
        __syncthreads();
        float acc2 = g1b2[tid];
        const float4* wr = (const float4*)(g1w2 + (size_t)tid * HH);
        const float4* y4 = (const float4*)y;
        #pragma unroll 8
        for (int q = 0; q < 64; q++) {
            float4 a = wr[q], bb = y4[q];
            acc2 += a.x * bb.x + a.y * bb.y + a.z * bb.z + a.w * bb.w;
        }
        g_h1[(size_t)row * HH + tid] = fmaxf(acc2, 0.0f);
        __syncthreads();
    }
}

// ---------------- K4: S1 = (512-nd)*uniform + sum(dirty h1) ------------------
__global__ void reduce_S1_kernel()
{
    int b = blockIdx.x, t = threadIdx.x;
    float u = g_h1[(size_t)b * HH + t];
    float s = (float)(NN - g_ndB[b]) * u;
    int nD = g_nDirty;
    for (int e = 0; e < nD; e++)
        if ((g_dirtyList[e] >> 9) == b) s += g_h1[(size_t)(64 + e) * HH + t];
    g_S1[b * HH + t] = s;
}

// ---------------- K5: agg1 + GIN2 + transformer x2 + head + scatter ----------
__global__ __launch_bounds__(256)
void rest_kernel(const float* __restrict__ g2w1, const float* __restrict__ g2b1,
                 const float* __restrict__ g2w2, const float* __restrict__ g2b2,
                 const float* __restrict__ t_in_w, const float* __restrict__ t_in_b,
                 const float* __restrict__ t_out_w, const float* __restrict__ t_out_b,
                 const float* __restrict__ t_ln1_g, const float* __restrict__ t_ln1_b,
                 const float* __restrict__ t_ff1_w, const float* __restrict__ t_ff1_b,
                 const float* __restrict__ t_ff2_w, const float* __restrict__ t_ff2_b,
                 const float* __restrict__ t_ln2_g, const float* __restrict__ t_ln2_b,
                 const float* __restrict__ fc_w, const float* __restrict__ fc_b,
                 float* __restrict__ out)
{
    __shared__ __align__(16) float X[256];
    __shared__ __align__(16) float T1[256];
    __shared__ __align__(16) float T2[256];
    __shared__ float red[16];
    __shared__ float out5[5];
    int tid = threadIdx.x, w = tid >> 5, lane = tid & 31;
    int nW = 64 + g_nDirty;

    auto gemv = [&](const float* src, float* dst, const float* W,
                    const float* bias, bool relu) {
        float acc = bias[tid];
        const float4* wr = (const float4*)(W + (size_t)tid * HH);
        const float4* s4 = (const float4*)src;
        #pragma unroll 8
        for (int q = 0; q < 64; q++) {
            float4 a = wr[q], xx = s4[q];
            acc += a.x * xx.x + a.y * xx.y + a.z * xx.z + a.w * xx.w;
        }
        dst[tid] = relu ? fmaxf(acc, 0.0f) : acc;
        __syncthreads();
    };
    auto lnf = [&](float* xv, const float* yv, const float* gg, const float* bb) {
        float v = xv[tid] + yv[tid];
        float s = v;
        #pragma unroll
        for (int off = 16; off; off >>= 1) s += __shfl_xor_sync(~0u, s, off);
        if (!lane) red[w] = s;
        __syncthreads();
        float tot = 0.0f;
        #pragma unroll
        for (int q = 0; q < 8; q++) tot += red[q];
        float mean = tot * (1.0f / 256.0f);
        float d = v - mean;
        float s2 = d * d;
        #pragma unroll
        for (int off = 16; off; off >>= 1) s2 += __shfl_xor_sync(~0u, s2, off);
        if (!lane) red[8 + w] = s2;
        __syncthreads();
        float tot2 = 0.0f;
        #pragma unroll
        for (int q = 0; q < 8; q++) tot2 += red[8 + q];
        float var = tot2 * (1.0f / 256.0f);
        xv[tid] = d / sqrtf(var + 1e-5f) * gg[tid] + bb[tid];
        __syncthreads();
    };

    for (int row = blockIdx.x; row < nW; row += gridDim.x) {
        int b;
        float v;
        if (row < 64) {
            b = row;
            v = g_S1[row * HH + tid];
        } else {
            int tok = g_dirtyList[row - 64];
            b = tok >> 9;
            v = g_S1[b * HH + tid];
            for (int wd = 0; wd < 16; wd++) {
                unsigned m = g_farmask[(size_t)tok * 16 + wd];
                while (m) {
                    int i = wd * 32 + __ffs(m) - 1; m &= m - 1;
                    int sl = g_slot[b * NN + i];     // far neighbor is dirty
                    v -= g_h1[(size_t)sl * HH + tid];
                }
            }
        }
        X[tid] = v;
        __syncthreads();

        // GIN2 MLP
        gemv(X, T1, g2w1, g2b1, true);
        gemv(T1, X, g2w2, g2b2, true);

        // transformer layers
        #pragma unroll 1
        for (int l = 0; l < 2; l++) {
            const float* Wv  = t_in_w + (size_t)l * 768 * HH + (size_t)512 * HH;
            const float* bv  = t_in_b + (size_t)l * 768 + 512;
            const float* Wo  = t_out_w + (size_t)l * HH * HH;
            const float* bo  = t_out_b + (size_t)l * HH;
            const float* l1g = t_ln1_g + (size_t)l * HH;
            const float* l1b = t_ln1_b + (size_t)l * HH;
            const float* W1  = t_ff1_w + (size_t)l * HH * HH;
            const float* b1  = t_ff1_b + (size_t)l * HH;
            const float* W2  = t_ff2_w + (size_t)l * HH * HH;
            const float* b2  = t_ff2_b + (size_t)l * HH;
            const float* l2g = t_ln2_g + (size_t)l * HH;
            const float* l2b = t_ln2_b + (size_t)l * HH;

            gemv(X, T1, Wv, bv, false);
            gemv(T1, T2, Wo, bo, false);
            lnf(X, T2, l1g, l1b);
            gemv(X, T1, W1, b1, true);
            gemv(T1, T2, W2, b2, false);
            lnf(X, T2, l2g, l2b);
        }

        // head (5 warps)
        if (w < 5) {
            const float* wr = fc_w + w * HH;
            float s = 0.0f;
            #pragma unroll
            for (int q = 0; q < 8; q++) s += X[lane + 32 * q] * wr[lane + 32 * q];
            #pragma unroll
            for (int off = 16; off; off >>= 1) s += __shfl_xor_sync(~0u, s, off);
            if (!lane) out5[w] = s + fc_b[w];
        }
        __syncthreads();

        // fused scatter
        if (row < 64) {
            for (int t = tid; t < NN; t += 256) {
                int tok = b * NN + t;
                if (g_slot[tok] < 0) {
                    float* o = out + (size_t)tok * 5;
                    o[0] = out5[0]; o[1] = out5[1]; o[2] = out5[2];
                    o[3] = out5[3]; o[4] = out5[4];
                }
            }
        } else {
            int tok = g_dirtyList[row - 64];
            if (tid < 5) out[(size_t)tok * 5 + tid] = out5[tid];
        }
        __syncthreads();
    }
}

// ---------------- launch ------------------------------------------------------
extern "C" void kernel_launch(void* const* d_in, const int* in_sizes, int n_in,
                              void* d_out, int out_size)
{
    const float* data   = (const float*)d_in[0];
    const float* lw1    = (const float*)d_in[1];
    const float* lb1    = (const float*)d_in[2];
    const float* lw2    = (const float*)d_in[3];
    const float* lb2    = (const float*)d_in[4];
    const float* g1w1   = (const float*)d_in[5];
    const float* g1b1   = (const float*)d_in[6];
    const float* g1w2   = (const float*)d_in[7];
    const float* g1b2   = (const float*)d_in[8];
    const float* g2w1   = (const float*)d_in[9];
    const float* g2b1   = (const float*)d_in[10];
    const float* g2w2   = (const float*)d_in[11];
    const float* g2b2   = (const float*)d_in[12];
    const float* t_in_w = (const float*)d_in[13];
    const float* t_in_b = (const float*)d_in[14];
    const float* t_out_w= (const float*)d_in[15];
    const float* t_out_b= (const float*)d_in[16];
    const float* t_ln1_g= (const float*)d_in[17];
    const float* t_ln1_b= (const float*)d_in[18];
    const float* t_ff1_w= (const float*)d_in[19];
    const float* t_ff1_b= (const float*)d_in[20];
    const float* t_ff2_w= (const float*)d_in[21];
    const float* t_ff2_b= (const float*)d_in[22];
    const float* t_ln2_g= (const float*)d_in[23];
    const float* t_ln2_b= (const float*)d_in[24];
    const float* fc_w   = (const float*)d_in[25];
    const float* fc_b   = (const float*)d_in[26];
    float* out = (float*)d_out;

    init_kernel<<<128, 256>>>();
    lidar32_kernel<<<TOKENS / 32, 256>>>(data, lw1, lb1, lw2, lb2);
    far_detect_kernel<<<BATCH, NN>>>(data);
    gin1_kernel<<<256, 256>>>(g1w1, g1b1, g1w2, g1b2);
    reduce_S1_kernel<<<BATCH, 256>>>();
    rest_kernel<<<256, 256>>>(g2w1, g2b1, g2w2, g2b2,
                              t_in_w, t_in_b, t_out_w, t_out_b,
                              t_ln1_g, t_ln1_b, t_ff1_w, t_ff1_b,
                              t_ff2_w, t_ff2_b, t_ln2_g, t_ln2_b,
                              fc_w, fc_b, out);
    (void)in_sizes; (void)n_in; (void)out_size;
}